// round 1
// baseline (speedup 1.0000x reference)
#include <cuda_runtime.h>
#include <cstdint>

// Problem constants
#define Bc   128          // batch (attention is over this axis!)
#define Sc   512
#define Dc   768
#define Hc   12
#define DHc  64
#define NTOK (Bc * Sc)    // 65536 tokens
#define NH   (Sc * Hc)    // 6144 independent attention problems
#define E3   (3 * Dc)     // 2304

// Scratch: allocation-free rule -> __device__ globals (bss, ~805MB total)
// qkv layout: [n=6144][which(q,k,v)][b=128][dh=64]
__device__ float g_qkv[(size_t)NH * 3 * Bc * DHc];
// ctx layout: [b][s][d]  (d = h*64+dh)
__device__ float g_ctx[(size_t)NTOK * Dc];

// ---------------------------------------------------------------------------
// GEMM: C[M,N] = A[M,K] * W[N,K]^T   (both K-major row-major)
// 128x128 CTA tile, BK=8, 256 threads, 8x8 per-thread register tile.
// MODE 0: A = X, epilogue adds bias and scatters into g_qkv layout.
// MODE 1: A = g_ctx (param ignored), epilogue writes row-major to Cout.
// ---------------------------------------------------------------------------
template <int MODE>
__global__ __launch_bounds__(256) void gemm_kernel(
    const float* __restrict__ A, const float* __restrict__ W,
    const float* __restrict__ bias, float* __restrict__ Cout,
    int M, int N, int K)
{
    __shared__ float As[8][128];
    __shared__ float Bs[8][128];

    const float* Ap = (MODE == 1) ? (const float*)g_ctx : A;

    const int tid = threadIdx.x;
    const int tx = tid & 15;        // 0..15 -> col block of 8
    const int ty = tid >> 4;        // 0..15 -> row block of 8
    const int rowBase = blockIdx.y * 128;
    const int colBase = blockIdx.x * 128;

    const int lr = tid >> 1;        // 0..127 row within tile for loading
    const int lk = (tid & 1) * 4;   // 0 or 4

    float acc[8][8];
#pragma unroll
    for (int i = 0; i < 8; i++)
#pragma unroll
        for (int j = 0; j < 8; j++) acc[i][j] = 0.f;

    for (int k0 = 0; k0 < K; k0 += 8) {
        float4 a = *(const float4*)(Ap + (size_t)(rowBase + lr) * K + k0 + lk);
        float4 b = *(const float4*)(W  + (size_t)(colBase + lr) * K + k0 + lk);
        __syncthreads();
        As[lk + 0][lr] = a.x; As[lk + 1][lr] = a.y;
        As[lk + 2][lr] = a.z; As[lk + 3][lr] = a.w;
        Bs[lk + 0][lr] = b.x; Bs[lk + 1][lr] = b.y;
        Bs[lk + 2][lr] = b.z; Bs[lk + 3][lr] = b.w;
        __syncthreads();
#pragma unroll
        for (int kk = 0; kk < 8; kk++) {
            float av[8], bv[8];
            *(float4*)(av)     = *(const float4*)&As[kk][ty * 8];
            *(float4*)(av + 4) = *(const float4*)&As[kk][ty * 8 + 4];
            *(float4*)(bv)     = *(const float4*)&Bs[kk][tx * 8];
            *(float4*)(bv + 4) = *(const float4*)&Bs[kk][tx * 8 + 4];
#pragma unroll
            for (int i = 0; i < 8; i++)
#pragma unroll
                for (int j = 0; j < 8; j++)
                    acc[i][j] += av[i] * bv[j];
        }
    }

    if (MODE == 0) {
        // scatter into g_qkv[n][w][b][dh], n = s*H + h, with bias
#pragma unroll
        for (int i = 0; i < 8; i++) {
            int m  = rowBase + ty * 8 + i;   // token = b*S + s
            int bb = m >> 9;                 // /512
            int ss = m & 511;
#pragma unroll
            for (int j = 0; j < 8; j++) {
                int e  = colBase + tx * 8 + j;
                float v = acc[i][j] + bias[e];
                int h  = e / 192;
                int r  = e - h * 192;
                int w  = r >> 6;
                int dh = r & 63;
                int n  = ss * Hc + h;
                g_qkv[(((size_t)n * 3 + w) * Bc + bb) * DHc + dh] = v;
            }
        }
    } else {
#pragma unroll
        for (int i = 0; i < 8; i++) {
            int m = rowBase + ty * 8 + i;
            float* dst = Cout + (size_t)m * N + colBase + tx * 8;
            float4 v0 = make_float4(acc[i][0], acc[i][1], acc[i][2], acc[i][3]);
            float4 v1 = make_float4(acc[i][4], acc[i][5], acc[i][6], acc[i][7]);
            *(float4*)(dst)     = v0;
            *(float4*)(dst + 4) = v1;
        }
    }
}

// ---------------------------------------------------------------------------
// Attention: one CTA per n (6144). 128x128 scores over batch axis, K=64.
// Mask: col <= row  -> -10000 (reference masks the LOWER triangle + diag).
// smem: Qt[64][132], Kt[64][132] (transposed, padded), Vs[128][64], Ps[128][128]
// ---------------------------------------------------------------------------
#define QK_STRIDE 132
#define SMEM_ATTN ((64 * QK_STRIDE * 2 + 128 * 64 + 128 * 128) * sizeof(float))

__global__ __launch_bounds__(256) void attn_kernel()
{
    extern __shared__ float sm[];
    float* Qt = sm;                          // 64*132
    float* Kt = Qt + 64 * QK_STRIDE;         // 64*132
    float* Vs = Kt + 64 * QK_STRIDE;         // 128*64
    float* Ps = Vs + 128 * 64;               // 128*128

    const int n   = blockIdx.x;
    const int tid = threadIdx.x;
    const float* qb = g_qkv + (size_t)n * 3 * Bc * DHc;
    const float* kb = qb + Bc * DHc;
    const float* vb = kb + Bc * DHc;

    // Load Q,K transposed (scalar, coalesced gmem reads, conflict-lite stores)
#pragma unroll
    for (int it = 0; it < 32; it++) {
        int idx = tid + it * 256;            // 0..8191
        int col = idx >> 6;                  // batch row 0..127
        int k   = idx & 63;
        Qt[k * QK_STRIDE + col] = qb[idx];
        Kt[k * QK_STRIDE + col] = kb[idx];
    }
    // V linear (float4)
#pragma unroll
    for (int it = 0; it < 8; it++) {
        int idx4 = tid + it * 256;           // 0..2047
        ((float4*)Vs)[idx4] = ((const float4*)vb)[idx4];
    }
    __syncthreads();

    const int tx = tid & 15;   // col block
    const int ty = tid >> 4;   // row block

    // ---- scores: 8x8 register tile per thread ----
    {
        float acc[8][8];
#pragma unroll
        for (int i = 0; i < 8; i++)
#pragma unroll
            for (int j = 0; j < 8; j++) acc[i][j] = 0.f;

#pragma unroll 4
        for (int k = 0; k < 64; k++) {
            float qv[8], kv[8];
            *(float4*)(qv)     = *(const float4*)&Qt[k * QK_STRIDE + ty * 8];
            *(float4*)(qv + 4) = *(const float4*)&Qt[k * QK_STRIDE + ty * 8 + 4];
            *(float4*)(kv)     = *(const float4*)&Kt[k * QK_STRIDE + tx * 8];
            *(float4*)(kv + 4) = *(const float4*)&Kt[k * QK_STRIDE + tx * 8 + 4];
#pragma unroll
            for (int i = 0; i < 8; i++)
#pragma unroll
                for (int j = 0; j < 8; j++)
                    acc[i][j] += qv[i] * kv[j];
        }

        const float scale = 0.125f;   // 1/sqrt(64)
#pragma unroll
        for (int i = 0; i < 8; i++) {
            int r = ty * 8 + i;
#pragma unroll
            for (int j = 0; j < 8; j++) {
                int c = tx * 8 + j;
                float s = acc[i][j] * scale;
                if (c <= r) s = -10000.0f;   // inverted causal mask per reference
                Ps[r * 128 + c] = s;
            }
        }
    }
    __syncthreads();

    // ---- softmax: one warp handles rows warp, warp+8, ... ----
    {
        int warp = tid >> 5, lane = tid & 31;
        for (int r = warp; r < 128; r += 8) {
            float v0 = Ps[r * 128 + lane];
            float v1 = Ps[r * 128 + lane + 32];
            float v2 = Ps[r * 128 + lane + 64];
            float v3 = Ps[r * 128 + lane + 96];
            float mx = fmaxf(fmaxf(v0, v1), fmaxf(v2, v3));
#pragma unroll
            for (int o = 16; o > 0; o >>= 1)
                mx = fmaxf(mx, __shfl_xor_sync(0xffffffffu, mx, o));
            float e0 = __expf(v0 - mx), e1 = __expf(v1 - mx);
            float e2 = __expf(v2 - mx), e3 = __expf(v3 - mx);
            float sum = e0 + e1 + e2 + e3;
#pragma unroll
            for (int o = 16; o > 0; o >>= 1)
                sum += __shfl_xor_sync(0xffffffffu, sum, o);
            float inv = 1.0f / sum;
            Ps[r * 128 + lane]      = e0 * inv;
            Ps[r * 128 + lane + 32] = e1 * inv;
            Ps[r * 128 + lane + 64] = e2 * inv;
            Ps[r * 128 + lane + 96] = e3 * inv;
        }
    }
    __syncthreads();

    // ---- ctx = P @ V : outputs 128x64. 8 rows x 4 cols per thread ----
    {
        float acc[8][4];
#pragma unroll
        for (int i = 0; i < 8; i++)
#pragma unroll
            for (int j = 0; j < 4; j++) acc[i][j] = 0.f;

#pragma unroll 4
        for (int c = 0; c < 128; c++) {
            float pv[8];
#pragma unroll
            for (int i = 0; i < 8; i++) pv[i] = Ps[(ty * 8 + i) * 128 + c];
            float vv[4];
            *(float4*)vv = *(const float4*)&Vs[c * 64 + tx * 4];
#pragma unroll
            for (int i = 0; i < 8; i++)
#pragma unroll
                for (int j = 0; j < 4; j++)
                    acc[i][j] += pv[i] * vv[j];
        }

        int s = n / Hc, h = n - (n / Hc) * Hc;
#pragma unroll
        for (int i = 0; i < 8; i++) {
            int bb = ty * 8 + i;   // batch row of the attention == output batch
            float* dst = g_ctx + ((size_t)bb * Sc + s) * Dc + h * 64 + tx * 4;
            *(float4*)dst = make_float4(acc[i][0], acc[i][1], acc[i][2], acc[i][3]);
        }
    }
}

// ---------------------------------------------------------------------------
extern "C" void kernel_launch(void* const* d_in, const int* in_sizes, int n_in,
                              void* d_out, int out_size)
{
    const float* X       = (const float*)d_in[0];
    const float* W_qkv   = (const float*)d_in[1];
    const float* b_qkv   = (const float*)d_in[2];
    const float* W_dense = (const float*)d_in[3];
    const float* b_dense = (const float*)d_in[4];
    float* out = (float*)d_out;

    (void)in_sizes; (void)n_in;

    cudaFuncSetAttribute(attn_kernel,
                         cudaFuncAttributeMaxDynamicSharedMemorySize,
                         (int)SMEM_ATTN);

    // 1) QKV GEMM + bias + scatter into attention layout
    {
        dim3 grid(E3 / 128, NTOK / 128);   // (18, 512)
        gemm_kernel<0><<<grid, 256>>>(X, W_qkv, b_qkv, nullptr,
                                      NTOK, E3, Dc);
    }

    // 2) Attention: 6144 independent 128x128x64 problems
    attn_kernel<<<NH, 256, SMEM_ATTN>>>();

    // 3) Dense GEMM: out = ctx @ W_dense^T  (b_dense NOT added; returned separately)
    {
        dim3 grid(Dc / 128, NTOK / 128);   // (6, 512)
        gemm_kernel<1><<<grid, 256>>>(nullptr, W_dense, nullptr, out,
                                      NTOK, Dc, Dc);
    }

    // 4) Reference returns (out, b_dense): append b_dense to the tail
    long long tail = (long long)out_size - (long long)NTOK * Dc;
    if (tail > 0) {
        if (tail > Dc) tail = Dc;
        cudaMemcpyAsync(out + (size_t)NTOK * Dc, b_dense,
                        (size_t)tail * sizeof(float),
                        cudaMemcpyDeviceToDevice, 0);
    }
}

// round 4
// speedup vs baseline: 3.4574x; 3.4574x over previous
#include <cuda_runtime.h>
#include <cstdint>

// ---------------------------------------------------------------- constants
#define Bc   128
#define Sc   512
#define Dc   768
#define Hc   12
#define DHc  64
#define NTOK (Bc * Sc)    // 65536
#define NH   (Sc * Hc)    // 6144
#define E3   (3 * Dc)     // 2304

// Scratch (allocation-free rule -> device globals)
__device__ float g_qkv[(size_t)NH * 3 * Bc * DHc];   // [n][qkv][b][dh]
__device__ float g_ctx[(size_t)NTOK * Dc];           // [b][s][d]

// ---------------------------------------------------------------- helpers
__device__ __forceinline__ uint32_t f2tf32(float x) {
    uint32_t r;
    asm("cvt.rna.tf32.f32 %0, %1;" : "=r"(r) : "f"(x));
    return r;
}

__device__ __forceinline__ void mma_tf32(float* c, const uint32_t* a,
                                         const uint32_t* b)
{
    asm volatile(
        "mma.sync.aligned.m16n8k8.row.col.f32.tf32.tf32.f32 "
        "{%0,%1,%2,%3}, {%4,%5,%6,%7}, {%8,%9}, {%0,%1,%2,%3};"
        : "+f"(c[0]), "+f"(c[1]), "+f"(c[2]), "+f"(c[3])
        : "r"(a[0]), "r"(a[1]), "r"(a[2]), "r"(a[3]),
          "r"(b[0]), "r"(b[1]));
}

// ---------------------------------------------------------------- tc GEMM
// C[M,N] = A[M,K] * W[N,K]^T  (W row-major [N][K] == B col-major [K][N])
// CTA 128x128, BK=16, 8 warps in 2x4 (warp tile 64x32), m16n8k8 tf32 mma.
// smem stride 20 floats -> conflict-free fragment loads.
#define BK    16
#define SSTR  20
#define TSZ   (128 * SSTR)   // floats per tile buffer

template <int MODE>
__global__ __launch_bounds__(256, 2) void gemm_mma(
    const float* __restrict__ A, const float* __restrict__ W,
    const float* __restrict__ bias, float* __restrict__ Cout,
    int K, int N)
{
    __shared__ uint32_t As[2][TSZ];
    __shared__ uint32_t Ws[2][TSZ];

    const float* Ap = (MODE == 1) ? (const float*)g_ctx : A;

    const int tid  = threadIdx.x;
    const int lane = tid & 31;
    const int warp = tid >> 5;
    const int wm   = warp & 1;          // 0..1 -> row 64-block
    const int wn   = warp >> 1;         // 0..3 -> col 32-block
    const int g    = lane >> 2;         // groupID 0..7
    const int t4   = lane & 3;          // threadID_in_group

    const int rowBase = blockIdx.y * 128;
    const int colBase = blockIdx.x * 128;

    // loader mapping: thread -> (row, half): 8 consecutive floats
    const int lr = tid >> 1;
    const int lc = (tid & 1) * 8;

    const float* gA = Ap + (size_t)(rowBase + lr) * K + lc;
    const float* gW = W  + (size_t)(colBase + lr) * K + lc;

    float acc[4][4][4];
#pragma unroll
    for (int i = 0; i < 4; i++)
#pragma unroll
        for (int j = 0; j < 4; j++)
#pragma unroll
            for (int k = 0; k < 4; k++) acc[i][j][k] = 0.f;

    const int nch = K / BK;

    // prefetch chunk 0
    float pa[8], pw[8];
    {
        *(float4*)(pa)     = *(const float4*)(gA);
        *(float4*)(pa + 4) = *(const float4*)(gA + 4);
        *(float4*)(pw)     = *(const float4*)(gW);
        *(float4*)(pw + 4) = *(const float4*)(gW + 4);
    }

    for (int ch = 0; ch < nch; ch++) {
        const int buf = ch & 1;
        // store prefetched chunk into smem (with tf32 rounding)
#pragma unroll
        for (int i = 0; i < 8; i++) {
            As[buf][lr * SSTR + lc + i] = f2tf32(pa[i]);
            Ws[buf][lr * SSTR + lc + i] = f2tf32(pw[i]);
        }
        __syncthreads();

        // prefetch next chunk while computing this one
        if (ch + 1 < nch) {
            const float* nA = gA + (ch + 1) * BK;
            const float* nW = gW + (ch + 1) * BK;
            *(float4*)(pa)     = *(const float4*)(nA);
            *(float4*)(pa + 4) = *(const float4*)(nA + 4);
            *(float4*)(pw)     = *(const float4*)(nW);
            *(float4*)(pw + 4) = *(const float4*)(nW + 4);
        }

#pragma unroll
        for (int ks = 0; ks < 2; ks++) {
            const int k0 = ks * 8;
            uint32_t af[4][4], bf[4][2];
#pragma unroll
            for (int mt = 0; mt < 4; mt++) {
                int r0 = wm * 64 + mt * 16 + g;
                af[mt][0] = As[buf][(r0)     * SSTR + k0 + t4];
                af[mt][1] = As[buf][(r0 + 8) * SSTR + k0 + t4];
                af[mt][2] = As[buf][(r0)     * SSTR + k0 + t4 + 4];
                af[mt][3] = As[buf][(r0 + 8) * SSTR + k0 + t4 + 4];
            }
#pragma unroll
            for (int nt = 0; nt < 4; nt++) {
                int c0 = wn * 32 + nt * 8 + g;
                bf[nt][0] = Ws[buf][c0 * SSTR + k0 + t4];
                bf[nt][1] = Ws[buf][c0 * SSTR + k0 + t4 + 4];
            }
#pragma unroll
            for (int mt = 0; mt < 4; mt++)
#pragma unroll
                for (int nt = 0; nt < 4; nt++)
                    mma_tf32(acc[mt][nt], af[mt], bf[nt]);
        }
        __syncthreads();
    }

    // ---- epilogue straight from registers ----
#pragma unroll
    for (int mt = 0; mt < 4; mt++) {
#pragma unroll
        for (int nt = 0; nt < 4; nt++) {
#pragma unroll
            for (int hi = 0; hi < 2; hi++) {       // c0/c1 vs c2/c3 (row +8)
                int r = rowBase + wm * 64 + mt * 16 + g + hi * 8;
                int c = colBase + wn * 32 + nt * 8 + 2 * t4;
                float v0 = acc[mt][nt][hi * 2 + 0];
                float v1 = acc[mt][nt][hi * 2 + 1];
                if (MODE == 0) {
                    int b  = r >> 9;               // token = b*512 + ss
                    int ss = r & 511;
#pragma unroll
                    for (int q = 0; q < 2; q++) {
                        int e = c + q;
                        float v = (q ? v1 : v0) + bias[e];
                        int h = e / 192, rr = e - h * 192;
                        int w = rr >> 6, dh = rr & 63;
                        int n = ss * Hc + h;
                        g_qkv[(((size_t)n * 3 + w) * Bc + b) * DHc + dh] = v;
                    }
                } else {
                    float2* dst = (float2*)(Cout + (size_t)r * N + c);
                    *dst = make_float2(v0, v1);
                }
            }
        }
    }
}

// ---------------------------------------------------------------- attention
// one CTA per n; 128x128 scores over batch axis, K=64; mask col<=row
#define QK_STRIDE 132
#define SMEM_ATTN ((64 * QK_STRIDE * 2 + 128 * 64 + 128 * 128) * sizeof(float))

__global__ __launch_bounds__(256) void attn_kernel()
{
    extern __shared__ float sm[];
    float* Qt = sm;
    float* Kt = Qt + 64 * QK_STRIDE;
    float* Vs = Kt + 64 * QK_STRIDE;
    float* Ps = Vs + 128 * 64;

    const int n   = blockIdx.x;
    const int tid = threadIdx.x;
    const float* qb = g_qkv + (size_t)n * 3 * Bc * DHc;
    const float* kb = qb + Bc * DHc;
    const float* vb = kb + Bc * DHc;

#pragma unroll
    for (int it = 0; it < 32; it++) {
        int idx = tid + it * 256;
        int col = idx >> 6;
        int k   = idx & 63;
        Qt[k * QK_STRIDE + col] = qb[idx];
        Kt[k * QK_STRIDE + col] = kb[idx];
    }
#pragma unroll
    for (int it = 0; it < 8; it++) {
        int idx4 = tid + it * 256;
        ((float4*)Vs)[idx4] = ((const float4*)vb)[idx4];
    }
    __syncthreads();

    const int tx = tid & 15;
    const int ty = tid >> 4;

    {
        float acc[8][8];
#pragma unroll
        for (int i = 0; i < 8; i++)
#pragma unroll
            for (int j = 0; j < 8; j++) acc[i][j] = 0.f;

#pragma unroll 4
        for (int k = 0; k < 64; k++) {
            float qv[8], kv[8];
            *(float4*)(qv)     = *(const float4*)&Qt[k * QK_STRIDE + ty * 8];
            *(float4*)(qv + 4) = *(const float4*)&Qt[k * QK_STRIDE + ty * 8 + 4];
            *(float4*)(kv)     = *(const float4*)&Kt[k * QK_STRIDE + tx * 8];
            *(float4*)(kv + 4) = *(const float4*)&Kt[k * QK_STRIDE + tx * 8 + 4];
#pragma unroll
            for (int i = 0; i < 8; i++)
#pragma unroll
                for (int j = 0; j < 8; j++)
                    acc[i][j] += qv[i] * kv[j];
        }

        const float scale = 0.125f;
#pragma unroll
        for (int i = 0; i < 8; i++) {
            int r = ty * 8 + i;
#pragma unroll
            for (int j = 0; j < 8; j++) {
                int c = tx * 8 + j;
                float s = acc[i][j] * scale;
                if (c <= r) s = -10000.0f;
                Ps[r * 128 + c] = s;
            }
        }
    }
    __syncthreads();

    {
        int warp = tid >> 5, lane = tid & 31;
        for (int r = warp; r < 128; r += 8) {
            float v0 = Ps[r * 128 + lane];
            float v1 = Ps[r * 128 + lane + 32];
            float v2 = Ps[r * 128 + lane + 64];
            float v3 = Ps[r * 128 + lane + 96];
            float mx = fmaxf(fmaxf(v0, v1), fmaxf(v2, v3));
#pragma unroll
            for (int o = 16; o > 0; o >>= 1)
                mx = fmaxf(mx, __shfl_xor_sync(0xffffffffu, mx, o));
            float e0 = __expf(v0 - mx), e1 = __expf(v1 - mx);
            float e2 = __expf(v2 - mx), e3 = __expf(v3 - mx);
            float sum = e0 + e1 + e2 + e3;
#pragma unroll
            for (int o = 16; o > 0; o >>= 1)
                sum += __shfl_xor_sync(0xffffffffu, sum, o);
            float inv = 1.0f / sum;
            Ps[r * 128 + lane]      = e0 * inv;
            Ps[r * 128 + lane + 32] = e1 * inv;
            Ps[r * 128 + lane + 64] = e2 * inv;
            Ps[r * 128 + lane + 96] = e3 * inv;
        }
    }
    __syncthreads();

    {
        float acc[8][4];
#pragma unroll
        for (int i = 0; i < 8; i++)
#pragma unroll
            for (int j = 0; j < 4; j++) acc[i][j] = 0.f;

#pragma unroll 4
        for (int c = 0; c < 128; c++) {
            float pv[8];
#pragma unroll
            for (int i = 0; i < 8; i++) pv[i] = Ps[(ty * 8 + i) * 128 + c];
            float vv[4];
            *(float4*)vv = *(const float4*)&Vs[c * 64 + tx * 4];
#pragma unroll
            for (int i = 0; i < 8; i++)
#pragma unroll
                for (int j = 0; j < 4; j++)
                    acc[i][j] += pv[i] * vv[j];
        }

        int s = n / Hc, h = n - (n / Hc) * Hc;
#pragma unroll
        for (int i = 0; i < 8; i++) {
            int bb = ty * 8 + i;
            float* dst = g_ctx + ((size_t)bb * Sc + s) * Dc + h * 64 + tx * 4;
            *(float4*)dst = make_float4(acc[i][0], acc[i][1], acc[i][2], acc[i][3]);
        }
    }
}

// ----------------------------------------------------------------
extern "C" void kernel_launch(void* const* d_in, const int* in_sizes, int n_in,
                              void* d_out, int out_size)
{
    const float* X       = (const float*)d_in[0];
    const float* W_qkv   = (const float*)d_in[1];
    const float* b_qkv   = (const float*)d_in[2];
    const float* W_dense = (const float*)d_in[3];
    const float* b_dense = (const float*)d_in[4];
    float* out = (float*)d_out;
    (void)in_sizes; (void)n_in;

    cudaFuncSetAttribute(attn_kernel,
                         cudaFuncAttributeMaxDynamicSharedMemorySize,
                         (int)SMEM_ATTN);

    // 1) QKV = X @ W_qkv^T + bias, scattered into [n][qkv][b][dh]
    gemm_mma<0><<<dim3(E3 / 128, NTOK / 128), 256>>>(
        X, W_qkv, b_qkv, nullptr, Dc, E3);

    // 2) attention (6144 independent 128x128x64 problems over batch axis)
    attn_kernel<<<NH, 256, SMEM_ATTN>>>();

    // 3) out = ctx @ W_dense^T (b_dense returned separately, not added)
    gemm_mma<1><<<dim3(Dc / 128, NTOK / 128), 256>>>(
        nullptr, W_dense, nullptr, out, Dc, Dc);

    // 4) tail: reference returns (out, b_dense)
    long long tail = (long long)out_size - (long long)NTOK * Dc;
    if (tail > 0) {
        if (tail > Dc) tail = Dc;
        cudaMemcpyAsync(out + (size_t)NTOK * Dc, b_dense,
                        (size_t)tail * sizeof(float),
                        cudaMemcpyDeviceToDevice, 0);
    }
}

// round 5
// speedup vs baseline: 3.7407x; 1.0819x over previous
#include <cuda_runtime.h>
#include <cstdint>

// ---------------------------------------------------------------- constants
#define Bc   128
#define Sc   512
#define Dc   768
#define Hc   12
#define DHc  64
#define NTOK (Bc * Sc)    // 65536
#define NH   (Sc * Hc)    // 6144
#define E3   (3 * Dc)     // 2304

// Scratch (allocation-free rule -> device globals)
__device__ float g_qkv[(size_t)NH * 3 * Bc * DHc];   // [n][qkv][b][dh]
__device__ float g_ctx[(size_t)NTOK * Dc];           // [b][s][d]

// ---------------------------------------------------------------- helpers
__device__ __forceinline__ uint32_t f2tf32(float x) {
    uint32_t r;
    asm("cvt.rna.tf32.f32 %0, %1;" : "=r"(r) : "f"(x));
    return r;
}

__device__ __forceinline__ void mma_tf32(float* c, const uint32_t* a,
                                         const uint32_t* b)
{
    asm volatile(
        "mma.sync.aligned.m16n8k8.row.col.f32.tf32.tf32.f32 "
        "{%0,%1,%2,%3}, {%4,%5,%6,%7}, {%8,%9}, {%0,%1,%2,%3};"
        : "+f"(c[0]), "+f"(c[1]), "+f"(c[2]), "+f"(c[3])
        : "r"(a[0]), "r"(a[1]), "r"(a[2]), "r"(a[3]),
          "r"(b[0]), "r"(b[1]));
}

// ---------------------------------------------------------------- tc GEMM
// (unchanged from round 4 — validated)
#define BK    16
#define SSTR  20
#define TSZ   (128 * SSTR)

template <int MODE>
__global__ __launch_bounds__(256, 2) void gemm_mma(
    const float* __restrict__ A, const float* __restrict__ W,
    const float* __restrict__ bias, float* __restrict__ Cout,
    int K, int N)
{
    __shared__ uint32_t As[2][TSZ];
    __shared__ uint32_t Ws[2][TSZ];

    const float* Ap = (MODE == 1) ? (const float*)g_ctx : A;

    const int tid  = threadIdx.x;
    const int lane = tid & 31;
    const int warp = tid >> 5;
    const int wm   = warp & 1;
    const int wn   = warp >> 1;
    const int g    = lane >> 2;
    const int t4   = lane & 3;

    const int rowBase = blockIdx.y * 128;
    const int colBase = blockIdx.x * 128;

    const int lr = tid >> 1;
    const int lc = (tid & 1) * 8;

    const float* gA = Ap + (size_t)(rowBase + lr) * K + lc;
    const float* gW = W  + (size_t)(colBase + lr) * K + lc;

    float acc[4][4][4];
#pragma unroll
    for (int i = 0; i < 4; i++)
#pragma unroll
        for (int j = 0; j < 4; j++)
#pragma unroll
            for (int k = 0; k < 4; k++) acc[i][j][k] = 0.f;

    const int nch = K / BK;

    float pa[8], pw[8];
    {
        *(float4*)(pa)     = *(const float4*)(gA);
        *(float4*)(pa + 4) = *(const float4*)(gA + 4);
        *(float4*)(pw)     = *(const float4*)(gW);
        *(float4*)(pw + 4) = *(const float4*)(gW + 4);
    }

    for (int ch = 0; ch < nch; ch++) {
        const int buf = ch & 1;
#pragma unroll
        for (int i = 0; i < 8; i++) {
            As[buf][lr * SSTR + lc + i] = f2tf32(pa[i]);
            Ws[buf][lr * SSTR + lc + i] = f2tf32(pw[i]);
        }
        __syncthreads();

        if (ch + 1 < nch) {
            const float* nA = gA + (ch + 1) * BK;
            const float* nW = gW + (ch + 1) * BK;
            *(float4*)(pa)     = *(const float4*)(nA);
            *(float4*)(pa + 4) = *(const float4*)(nA + 4);
            *(float4*)(pw)     = *(const float4*)(nW);
            *(float4*)(pw + 4) = *(const float4*)(nW + 4);
        }

#pragma unroll
        for (int ks = 0; ks < 2; ks++) {
            const int k0 = ks * 8;
            uint32_t af[4][4], bf[4][2];
#pragma unroll
            for (int mt = 0; mt < 4; mt++) {
                int r0 = wm * 64 + mt * 16 + g;
                af[mt][0] = As[buf][(r0)     * SSTR + k0 + t4];
                af[mt][1] = As[buf][(r0 + 8) * SSTR + k0 + t4];
                af[mt][2] = As[buf][(r0)     * SSTR + k0 + t4 + 4];
                af[mt][3] = As[buf][(r0 + 8) * SSTR + k0 + t4 + 4];
            }
#pragma unroll
            for (int nt = 0; nt < 4; nt++) {
                int c0 = wn * 32 + nt * 8 + g;
                bf[nt][0] = Ws[buf][c0 * SSTR + k0 + t4];
                bf[nt][1] = Ws[buf][c0 * SSTR + k0 + t4 + 4];
            }
#pragma unroll
            for (int mt = 0; mt < 4; mt++)
#pragma unroll
                for (int nt = 0; nt < 4; nt++)
                    mma_tf32(acc[mt][nt], af[mt], bf[nt]);
        }
        __syncthreads();
    }

#pragma unroll
    for (int mt = 0; mt < 4; mt++) {
#pragma unroll
        for (int nt = 0; nt < 4; nt++) {
#pragma unroll
            for (int hi = 0; hi < 2; hi++) {
                int r = rowBase + wm * 64 + mt * 16 + g + hi * 8;
                int c = colBase + wn * 32 + nt * 8 + 2 * t4;
                float v0 = acc[mt][nt][hi * 2 + 0];
                float v1 = acc[mt][nt][hi * 2 + 1];
                if (MODE == 0) {
                    int b  = r >> 9;
                    int ss = r & 511;
#pragma unroll
                    for (int q = 0; q < 2; q++) {
                        int e = c + q;
                        float v = (q ? v1 : v0) + bias[e];
                        int h = e / 192, rr = e - h * 192;
                        int w = rr >> 6, dh = rr & 63;
                        int n = ss * Hc + h;
                        g_qkv[(((size_t)n * 3 + w) * Bc + b) * DHc + dh] = v;
                    }
                } else {
                    float2* dst = (float2*)(Cout + (size_t)r * N + c);
                    *dst = make_float2(v0, v1);
                }
            }
        }
    }
}

// ---------------------------------------------------------------- attention
// one CTA per n; tf32 mma for scores (128x128x64) and PV (128x64x128).
// smem (floats): Qs[128][68], Ks[128][68], Vt[64][132]; Ps[128][132] aliases Qs/Ks.
#define QP 68
#define PP 132
#define OFF_KS (128 * QP)          // 8704
#define OFF_VT (2 * 128 * QP)      // 17408
#define ATTN_FLOATS (OFF_VT + 64 * PP)   // 25856
#define SMEM_ATTN (ATTN_FLOATS * 4)      // 103424 B

__global__ __launch_bounds__(256, 1) void attn_kernel()
{
    extern __shared__ float sm[];
    uint32_t* Qs = (uint32_t*)sm;
    uint32_t* Ks = (uint32_t*)sm + OFF_KS;
    uint32_t* Vt = (uint32_t*)sm + OFF_VT;
    float*    Ps = sm;                       // aliases Qs/Ks after scores

    const int n   = blockIdx.x;
    const int tid = threadIdx.x;
    const int lane = tid & 31;
    const int warp = tid >> 5;
    const int wm = warp & 1;      // row 64-block (b)
    const int wn = warp >> 1;     // col block
    const int g  = lane >> 2;
    const int t4 = lane & 3;

    const float* qb = g_qkv + (size_t)n * 3 * Bc * DHc;
    const float* kb = qb + Bc * DHc;
    const float* vb = kb + Bc * DHc;

    // stage Q,K native [b][dh] (tf32), V transposed Vt[dh][c] (tf32)
#pragma unroll
    for (int it = 0; it < 32; it++) {
        int idx = tid + it * 256;         // 0..8191
        int r  = idx >> 6;
        int dh = idx & 63;
        Qs[r * QP + dh] = f2tf32(qb[idx]);
        Ks[r * QP + dh] = f2tf32(kb[idx]);
        Vt[dh * PP + r] = f2tf32(vb[idx]);
    }
    __syncthreads();

    // ---- scores: S = Q K^T, 128x128, K=64 ----
    float acc[4][4][4];
#pragma unroll
    for (int i = 0; i < 4; i++)
#pragma unroll
        for (int j = 0; j < 4; j++)
#pragma unroll
            for (int k = 0; k < 4; k++) acc[i][j][k] = 0.f;

#pragma unroll
    for (int ks = 0; ks < 8; ks++) {
        const int k0 = ks * 8;
        uint32_t af[4][4], bf[4][2];
#pragma unroll
        for (int mt = 0; mt < 4; mt++) {
            int r0 = wm * 64 + mt * 16 + g;
            af[mt][0] = Qs[(r0)     * QP + k0 + t4];
            af[mt][1] = Qs[(r0 + 8) * QP + k0 + t4];
            af[mt][2] = Qs[(r0)     * QP + k0 + t4 + 4];
            af[mt][3] = Qs[(r0 + 8) * QP + k0 + t4 + 4];
        }
#pragma unroll
        for (int nt = 0; nt < 4; nt++) {
            int c0 = wn * 32 + nt * 8 + g;
            bf[nt][0] = Ks[c0 * QP + k0 + t4];
            bf[nt][1] = Ks[c0 * QP + k0 + t4 + 4];
        }
#pragma unroll
        for (int mt = 0; mt < 4; mt++)
#pragma unroll
            for (int nt = 0; nt < 4; nt++)
                mma_tf32(acc[mt][nt], af[mt], bf[nt]);
    }
    __syncthreads();   // all Qs/Ks reads done; Ps may overwrite

    // mask + scale -> Ps (float)
    const float scale = 0.125f;
#pragma unroll
    for (int mt = 0; mt < 4; mt++)
#pragma unroll
        for (int nt = 0; nt < 4; nt++)
#pragma unroll
            for (int hi = 0; hi < 2; hi++) {
                int r = wm * 64 + mt * 16 + g + hi * 8;
                int c = wn * 32 + nt * 8 + 2 * t4;
#pragma unroll
                for (int q = 0; q < 2; q++) {
                    float s = acc[mt][nt][hi * 2 + q] * scale;
                    if (c + q <= r) s = -10000.0f;
                    Ps[r * PP + c + q] = s;
                }
            }
    __syncthreads();

    // ---- softmax rows (store tf32 bits for the PV mma) ----
    for (int r = warp; r < 128; r += 8) {
        float v0 = Ps[r * PP + lane];
        float v1 = Ps[r * PP + lane + 32];
        float v2 = Ps[r * PP + lane + 64];
        float v3 = Ps[r * PP + lane + 96];
        float mx = fmaxf(fmaxf(v0, v1), fmaxf(v2, v3));
#pragma unroll
        for (int o = 16; o > 0; o >>= 1)
            mx = fmaxf(mx, __shfl_xor_sync(0xffffffffu, mx, o));
        float e0 = __expf(v0 - mx), e1 = __expf(v1 - mx);
        float e2 = __expf(v2 - mx), e3 = __expf(v3 - mx);
        float sum = e0 + e1 + e2 + e3;
#pragma unroll
        for (int o = 16; o > 0; o >>= 1)
            sum += __shfl_xor_sync(0xffffffffu, sum, o);
        float inv = 1.0f / sum;
        Ps[r * PP + lane]      = __uint_as_float(f2tf32(e0 * inv));
        Ps[r * PP + lane + 32] = __uint_as_float(f2tf32(e1 * inv));
        Ps[r * PP + lane + 64] = __uint_as_float(f2tf32(e2 * inv));
        Ps[r * PP + lane + 96] = __uint_as_float(f2tf32(e3 * inv));
    }
    __syncthreads();

    // ---- ctx = P V : 128x64, K=128 ----
    const uint32_t* Pu = (const uint32_t*)Ps;
    float acc2[4][2][4];
#pragma unroll
    for (int i = 0; i < 4; i++)
#pragma unroll
        for (int j = 0; j < 2; j++)
#pragma unroll
            for (int k = 0; k < 4; k++) acc2[i][j][k] = 0.f;

#pragma unroll
    for (int ks = 0; ks < 16; ks++) {
        const int k0 = ks * 8;
        uint32_t af[4][4], bf[2][2];
#pragma unroll
        for (int mt = 0; mt < 4; mt++) {
            int r0 = wm * 64 + mt * 16 + g;
            af[mt][0] = Pu[(r0)     * PP + k0 + t4];
            af[mt][1] = Pu[(r0 + 8) * PP + k0 + t4];
            af[mt][2] = Pu[(r0)     * PP + k0 + t4 + 4];
            af[mt][3] = Pu[(r0 + 8) * PP + k0 + t4 + 4];
        }
#pragma unroll
        for (int nt = 0; nt < 2; nt++) {
            int c0 = wn * 16 + nt * 8 + g;      // dh index
            bf[nt][0] = Vt[c0 * PP + k0 + t4];
            bf[nt][1] = Vt[c0 * PP + k0 + t4 + 4];
        }
#pragma unroll
        for (int mt = 0; mt < 4; mt++)
#pragma unroll
            for (int nt = 0; nt < 2; nt++)
                mma_tf32(acc2[mt][nt], af[mt], bf[nt]);
    }

    // epilogue -> g_ctx[b][s][h*64+dh]
    const int s = n / Hc;
    const int h = n - s * Hc;
#pragma unroll
    for (int mt = 0; mt < 4; mt++)
#pragma unroll
        for (int nt = 0; nt < 2; nt++)
#pragma unroll
            for (int hi = 0; hi < 2; hi++) {
                int b  = wm * 64 + mt * 16 + g + hi * 8;
                int dh = wn * 16 + nt * 8 + 2 * t4;
                float2* dst = (float2*)(g_ctx +
                    ((size_t)b * Sc + s) * Dc + h * 64 + dh);
                *dst = make_float2(acc2[mt][nt][hi * 2 + 0],
                                   acc2[mt][nt][hi * 2 + 1]);
            }
}

// ----------------------------------------------------------------
extern "C" void kernel_launch(void* const* d_in, const int* in_sizes, int n_in,
                              void* d_out, int out_size)
{
    const float* X       = (const float*)d_in[0];
    const float* W_qkv   = (const float*)d_in[1];
    const float* b_qkv   = (const float*)d_in[2];
    const float* W_dense = (const float*)d_in[3];
    const float* b_dense = (const float*)d_in[4];
    float* out = (float*)d_out;
    (void)in_sizes; (void)n_in;

    cudaFuncSetAttribute(attn_kernel,
                         cudaFuncAttributeMaxDynamicSharedMemorySize,
                         SMEM_ATTN);

    // 1) QKV = X @ W_qkv^T + bias -> g_qkv[n][qkv][b][dh]
    gemm_mma<0><<<dim3(E3 / 128, NTOK / 128), 256>>>(
        X, W_qkv, b_qkv, nullptr, Dc, E3);

    // 2) attention (6144 independent 128x128x64 problems over batch axis)
    attn_kernel<<<NH, 256, SMEM_ATTN>>>();

    // 3) out = ctx @ W_dense^T (b_dense returned separately, not added)
    gemm_mma<1><<<dim3(Dc / 128, NTOK / 128), 256>>>(
        nullptr, W_dense, nullptr, out, Dc, Dc);

    // 4) tail: reference returns (out, b_dense)
    long long tail = (long long)out_size - (long long)NTOK * Dc;
    if (tail > 0) {
        if (tail > Dc) tail = Dc;
        cudaMemcpyAsync(out + (size_t)NTOK * Dc, b_dense,
                        (size_t)tail * sizeof(float),
                        cudaMemcpyDeviceToDevice, 0);
    }
}

// round 7
// speedup vs baseline: 4.8523x; 1.2971x over previous
#include <cuda_runtime.h>
#include <cstdint>

// ---------------------------------------------------------------- constants
#define Bc   128
#define Sc   512
#define Dc   768
#define Hc   12
#define DHc  64
#define NTOK (Bc * Sc)    // 65536
#define NH   (Sc * Hc)    // 6144
#define E3   (3 * Dc)     // 2304

// Scratch (allocation-free rule -> device globals)
__device__ float g_qkv[(size_t)NH * 3 * Bc * DHc];   // [n][qkv][b][dh]
__device__ float g_ctx[(size_t)NTOK * Dc];           // [b][s][d]

// ---------------------------------------------------------------- helpers
__device__ __forceinline__ uint32_t f2tf32(float x) {
    uint32_t r;
    asm("cvt.rna.tf32.f32 %0, %1;" : "=r"(r) : "f"(x));
    return r;
}
__device__ __forceinline__ uint32_t u2tf32(uint32_t xb) {
    uint32_t r;
    asm("cvt.rna.tf32.f32 %0, %1;" : "=r"(r) : "f"(__uint_as_float(xb)));
    return r;
}

__device__ __forceinline__ void mma_tf32(float* c, const uint32_t* a,
                                         const uint32_t* b)
{
    asm volatile(
        "mma.sync.aligned.m16n8k8.row.col.f32.tf32.tf32.f32 "
        "{%0,%1,%2,%3}, {%4,%5,%6,%7}, {%8,%9}, {%0,%1,%2,%3};"
        : "+f"(c[0]), "+f"(c[1]), "+f"(c[2]), "+f"(c[3])
        : "r"(a[0]), "r"(a[1]), "r"(a[2]), "r"(a[3]),
          "r"(b[0]), "r"(b[1]));
}

__device__ __forceinline__ uint32_t smem_u32(const void* p) {
    uint32_t a;
    asm("{ .reg .u64 t; cvta.to.shared.u64 t, %1; cvt.u32.u64 %0, t; }"
        : "=r"(a) : "l"(p));
    return a;
}
__device__ __forceinline__ void cp_async16(uint32_t dst, const void* src) {
    asm volatile("cp.async.cg.shared.global [%0], [%1], 16;"
                 :: "r"(dst), "l"(src));
}
#define CP_COMMIT() asm volatile("cp.async.commit_group;" ::: "memory")
#define CP_WAIT2()  asm volatile("cp.async.wait_group 2;" ::: "memory")

// ---------------------------------------------------------------- tc GEMM
// C[M,N] = A[M,K] * W[N,K]^T, CTA 128x128, BK=16, 8 warps (2x4, 64x32 tiles),
// m16n8k8 tf32 mma, 4-stage cp.async pipeline, 1 barrier per chunk.
// smem raw fp32; tf32 cvt at fragment load. SSTR=20 -> conflict-free.
#define BK    16
#define SSTR  20
#define TSZ   (128 * SSTR)                 // 2560 words / tile
#define SMEM_GEMM (8 * TSZ * 4)            // 4 stages * (A+W) = 81920 B

template <int MODE>
__global__ __launch_bounds__(256, 2) void gemm_mma(
    const float* __restrict__ A, const float* __restrict__ W,
    const float* __restrict__ bias, float* __restrict__ Cout,
    int K, int N)
{
    extern __shared__ uint32_t dynsm[];
    uint32_t* As = dynsm;                  // [4][TSZ]
    uint32_t* Ws = dynsm + 4 * TSZ;        // [4][TSZ]

    const float* Ap = (MODE == 1) ? (const float*)g_ctx : A;

    const int tid  = threadIdx.x;
    const int lane = tid & 31;
    const int warp = tid >> 5;
    const int wm   = warp & 1;
    const int wn   = warp >> 1;
    const int g    = lane >> 2;
    const int t4   = lane & 3;

    const int rowBase = blockIdx.y * 128;
    const int colBase = blockIdx.x * 128;

    // loader mapping: thread -> (row lr, 8-float half lc)
    const int lr = tid >> 1;
    const int lc = (tid & 1) * 8;

    const float* gA = Ap + (size_t)(rowBase + lr) * K + lc;
    const float* gW = W  + (size_t)(colBase + lr) * K + lc;

    const uint32_t sA = smem_u32(As) + (uint32_t)(lr * SSTR + lc) * 4;
    const uint32_t sW = smem_u32(Ws) + (uint32_t)(lr * SSTR + lc) * 4;

    const int nch = K / BK;   // 48

    // prologue: fill 3 stages
#pragma unroll
    for (int p = 0; p < 3; p++) {
        uint32_t da = sA + (uint32_t)((p & 3) * TSZ) * 4;
        uint32_t dw = sW + (uint32_t)((p & 3) * TSZ) * 4;
        const float* ga = gA + p * BK;
        const float* gw = gW + p * BK;
        cp_async16(da,      ga);
        cp_async16(da + 16, ga + 4);
        cp_async16(dw,      gw);
        cp_async16(dw + 16, gw + 4);
        CP_COMMIT();
    }

    float acc[4][4][4];
#pragma unroll
    for (int i = 0; i < 4; i++)
#pragma unroll
        for (int j = 0; j < 4; j++)
#pragma unroll
            for (int k = 0; k < 4; k++) acc[i][j][k] = 0.f;

    for (int ch = 0; ch < nch; ch++) {
        CP_WAIT2();
        __syncthreads();

        // issue stage ch+3 (empty commit keeps group accounting uniform)
        if (ch + 3 < nch) {
            int st = (ch + 3) & 3;
            uint32_t da = sA + (uint32_t)(st * TSZ) * 4;
            uint32_t dw = sW + (uint32_t)(st * TSZ) * 4;
            const float* ga = gA + (ch + 3) * BK;
            const float* gw = gW + (ch + 3) * BK;
            cp_async16(da,      ga);
            cp_async16(da + 16, ga + 4);
            cp_async16(dw,      gw);
            cp_async16(dw + 16, gw + 4);
        }
        CP_COMMIT();

        const uint32_t* Ab = As + (ch & 3) * TSZ;
        const uint32_t* Wb = Ws + (ch & 3) * TSZ;
#pragma unroll
        for (int ks = 0; ks < 2; ks++) {
            const int k0 = ks * 8;
            uint32_t af[4][4], bf[4][2];
#pragma unroll
            for (int mt = 0; mt < 4; mt++) {
                int r0 = wm * 64 + mt * 16 + g;
                af[mt][0] = u2tf32(Ab[(r0)     * SSTR + k0 + t4]);
                af[mt][1] = u2tf32(Ab[(r0 + 8) * SSTR + k0 + t4]);
                af[mt][2] = u2tf32(Ab[(r0)     * SSTR + k0 + t4 + 4]);
                af[mt][3] = u2tf32(Ab[(r0 + 8) * SSTR + k0 + t4 + 4]);
            }
#pragma unroll
            for (int nt = 0; nt < 4; nt++) {
                int c0 = wn * 32 + nt * 8 + g;
                bf[nt][0] = u2tf32(Wb[c0 * SSTR + k0 + t4]);
                bf[nt][1] = u2tf32(Wb[c0 * SSTR + k0 + t4 + 4]);
            }
#pragma unroll
            for (int mt = 0; mt < 4; mt++)
#pragma unroll
                for (int nt = 0; nt < 4; nt++)
                    mma_tf32(acc[mt][nt], af[mt], bf[nt]);
        }
    }

    // ---- epilogue straight from registers (unchanged) ----
#pragma unroll
    for (int mt = 0; mt < 4; mt++) {
#pragma unroll
        for (int nt = 0; nt < 4; nt++) {
#pragma unroll
            for (int hi = 0; hi < 2; hi++) {
                int r = rowBase + wm * 64 + mt * 16 + g + hi * 8;
                int c = colBase + wn * 32 + nt * 8 + 2 * t4;
                float v0 = acc[mt][nt][hi * 2 + 0];
                float v1 = acc[mt][nt][hi * 2 + 1];
                if (MODE == 0) {
                    int b  = r >> 9;
                    int ss = r & 511;
#pragma unroll
                    for (int q = 0; q < 2; q++) {
                        int e = c + q;
                        float v = (q ? v1 : v0) + bias[e];
                        int h = e / 192, rr = e - h * 192;
                        int w = rr >> 6, dh = rr & 63;
                        int n = ss * Hc + h;
                        g_qkv[(((size_t)n * 3 + w) * Bc + b) * DHc + dh] = v;
                    }
                } else {
                    float2* dst = (float2*)(Cout + (size_t)r * N + c);
                    *dst = make_float2(v0, v1);
                }
            }
        }
    }
}

// ---------------------------------------------------------------- attention
// (unchanged from round 5 — validated, ~0.4ms)
#define QP 68
#define PP 132
#define OFF_KS (128 * QP)
#define OFF_VT (2 * 128 * QP)
#define ATTN_FLOATS (OFF_VT + 64 * PP)
#define SMEM_ATTN (ATTN_FLOATS * 4)

__global__ __launch_bounds__(256, 1) void attn_kernel()
{
    extern __shared__ float sm[];
    uint32_t* Qs = (uint32_t*)sm;
    uint32_t* Ks = (uint32_t*)sm + OFF_KS;
    uint32_t* Vt = (uint32_t*)sm + OFF_VT;
    float*    Ps = sm;

    const int n   = blockIdx.x;
    const int tid = threadIdx.x;
    const int lane = tid & 31;
    const int warp = tid >> 5;
    const int wm = warp & 1;
    const int wn = warp >> 1;
    const int g  = lane >> 2;
    const int t4 = lane & 3;

    const float* qb = g_qkv + (size_t)n * 3 * Bc * DHc;
    const float* kb = qb + Bc * DHc;
    const float* vb = kb + Bc * DHc;

#pragma unroll
    for (int it = 0; it < 32; it++) {
        int idx = tid + it * 256;
        int r  = idx >> 6;
        int dh = idx & 63;
        Qs[r * QP + dh] = f2tf32(qb[idx]);
        Ks[r * QP + dh] = f2tf32(kb[idx]);
        Vt[dh * PP + r] = f2tf32(vb[idx]);
    }
    __syncthreads();

    float acc[4][4][4];
#pragma unroll
    for (int i = 0; i < 4; i++)
#pragma unroll
        for (int j = 0; j < 4; j++)
#pragma unroll
            for (int k = 0; k < 4; k++) acc[i][j][k] = 0.f;

#pragma unroll
    for (int ks = 0; ks < 8; ks++) {
        const int k0 = ks * 8;
        uint32_t af[4][4], bf[4][2];
#pragma unroll
        for (int mt = 0; mt < 4; mt++) {
            int r0 = wm * 64 + mt * 16 + g;
            af[mt][0] = Qs[(r0)     * QP + k0 + t4];
            af[mt][1] = Qs[(r0 + 8) * QP + k0 + t4];
            af[mt][2] = Qs[(r0)     * QP + k0 + t4 + 4];
            af[mt][3] = Qs[(r0 + 8) * QP + k0 + t4 + 4];
        }
#pragma unroll
        for (int nt = 0; nt < 4; nt++) {
            int c0 = wn * 32 + nt * 8 + g;
            bf[nt][0] = Ks[c0 * QP + k0 + t4];
            bf[nt][1] = Ks[c0 * QP + k0 + t4 + 4];
        }
#pragma unroll
        for (int mt = 0; mt < 4; mt++)
#pragma unroll
            for (int nt = 0; nt < 4; nt++)
                mma_tf32(acc[mt][nt], af[mt], bf[nt]);
    }
    __syncthreads();

    const float scale = 0.125f;
#pragma unroll
    for (int mt = 0; mt < 4; mt++)
#pragma unroll
        for (int nt = 0; nt < 4; nt++)
#pragma unroll
            for (int hi = 0; hi < 2; hi++) {
                int r = wm * 64 + mt * 16 + g + hi * 8;
                int c = wn * 32 + nt * 8 + 2 * t4;
#pragma unroll
                for (int q = 0; q < 2; q++) {
                    float s = acc[mt][nt][hi * 2 + q] * scale;
                    if (c + q <= r) s = -10000.0f;
                    Ps[r * PP + c + q] = s;
                }
            }
    __syncthreads();

    for (int r = warp; r < 128; r += 8) {
        float v0 = Ps[r * PP + lane];
        float v1 = Ps[r * PP + lane + 32];
        float v2 = Ps[r * PP + lane + 64];
        float v3 = Ps[r * PP + lane + 96];
        float mx = fmaxf(fmaxf(v0, v1), fmaxf(v2, v3));
#pragma unroll
        for (int o = 16; o > 0; o >>= 1)
            mx = fmaxf(mx, __shfl_xor_sync(0xffffffffu, mx, o));
        float e0 = __expf(v0 - mx), e1 = __expf(v1 - mx);
        float e2 = __expf(v2 - mx), e3 = __expf(v3 - mx);
        float sum = e0 + e1 + e2 + e3;
#pragma unroll
        for (int o = 16; o > 0; o >>= 1)
            sum += __shfl_xor_sync(0xffffffffu, sum, o);
        float inv = 1.0f / sum;
        Ps[r * PP + lane]      = __uint_as_float(f2tf32(e0 * inv));
        Ps[r * PP + lane + 32] = __uint_as_float(f2tf32(e1 * inv));
        Ps[r * PP + lane + 64] = __uint_as_float(f2tf32(e2 * inv));
        Ps[r * PP + lane + 96] = __uint_as_float(f2tf32(e3 * inv));
    }
    __syncthreads();

    const uint32_t* Pu = (const uint32_t*)Ps;
    float acc2[4][2][4];
#pragma unroll
    for (int i = 0; i < 4; i++)
#pragma unroll
        for (int j = 0; j < 2; j++)
#pragma unroll
            for (int k = 0; k < 4; k++) acc2[i][j][k] = 0.f;

#pragma unroll
    for (int ks = 0; ks < 16; ks++) {
        const int k0 = ks * 8;
        uint32_t af[4][4], bf[2][2];
#pragma unroll
        for (int mt = 0; mt < 4; mt++) {
            int r0 = wm * 64 + mt * 16 + g;
            af[mt][0] = Pu[(r0)     * PP + k0 + t4];
            af[mt][1] = Pu[(r0 + 8) * PP + k0 + t4];
            af[mt][2] = Pu[(r0)     * PP + k0 + t4 + 4];
            af[mt][3] = Pu[(r0 + 8) * PP + k0 + t4 + 4];
        }
#pragma unroll
        for (int nt = 0; nt < 2; nt++) {
            int c0 = wn * 16 + nt * 8 + g;
            bf[nt][0] = Vt[c0 * PP + k0 + t4];
            bf[nt][1] = Vt[c0 * PP + k0 + t4 + 4];
        }
#pragma unroll
        for (int mt = 0; mt < 4; mt++)
#pragma unroll
            for (int nt = 0; nt < 2; nt++)
                mma_tf32(acc2[mt][nt], af[mt], bf[nt]);
    }

    const int s = n / Hc;
    const int h = n - s * Hc;
#pragma unroll
    for (int mt = 0; mt < 4; mt++)
#pragma unroll
        for (int nt = 0; nt < 2; nt++)
#pragma unroll
            for (int hi = 0; hi < 2; hi++) {
                int b  = wm * 64 + mt * 16 + g + hi * 8;
                int dh = wn * 16 + nt * 8 + 2 * t4;
                float2* dst = (float2*)(g_ctx +
                    ((size_t)b * Sc + s) * Dc + h * 64 + dh);
                *dst = make_float2(acc2[mt][nt][hi * 2 + 0],
                                   acc2[mt][nt][hi * 2 + 1]);
            }
}

// ----------------------------------------------------------------
extern "C" void kernel_launch(void* const* d_in, const int* in_sizes, int n_in,
                              void* d_out, int out_size)
{
    const float* X       = (const float*)d_in[0];
    const float* W_qkv   = (const float*)d_in[1];
    const float* b_qkv   = (const float*)d_in[2];
    const float* W_dense = (const float*)d_in[3];
    const float* b_dense = (const float*)d_in[4];
    float* out = (float*)d_out;
    (void)in_sizes; (void)n_in;

    cudaFuncSetAttribute(gemm_mma<0>,
                         cudaFuncAttributeMaxDynamicSharedMemorySize, SMEM_GEMM);
    cudaFuncSetAttribute(gemm_mma<1>,
                         cudaFuncAttributeMaxDynamicSharedMemorySize, SMEM_GEMM);
    cudaFuncSetAttribute(attn_kernel,
                         cudaFuncAttributeMaxDynamicSharedMemorySize, SMEM_ATTN);

    // 1) QKV = X @ W_qkv^T + bias -> g_qkv[n][qkv][b][dh]
    gemm_mma<0><<<dim3(E3 / 128, NTOK / 128), 256, SMEM_GEMM>>>(
        X, W_qkv, b_qkv, nullptr, Dc, E3);

    // 2) attention (6144 independent 128x128x64 problems over batch axis)
    attn_kernel<<<NH, 256, SMEM_ATTN>>>();

    // 3) out = ctx @ W_dense^T (b_dense returned separately, not added)
    gemm_mma<1><<<dim3(Dc / 128, NTOK / 128), 256, SMEM_GEMM>>>(
        nullptr, W_dense, nullptr, out, Dc, Dc);

    // 4) tail: reference returns (out, b_dense)
    long long tail = (long long)out_size - (long long)NTOK * Dc;
    if (tail > 0) {
        if (tail > Dc) tail = Dc;
        cudaMemcpyAsync(out + (size_t)NTOK * Dc, b_dense,
                        (size_t)tail * sizeof(float),
                        cudaMemcpyDeviceToDevice, 0);
    }
}

// round 8
// speedup vs baseline: 4.9051x; 1.0109x over previous
#include <cuda_runtime.h>
#include <cstdint>

// ---------------------------------------------------------------- constants
#define Bc   128
#define Sc   512
#define Dc   768
#define Hc   12
#define DHc  64
#define NTOK (Bc * Sc)    // 65536
#define NH   (Sc * Hc)    // 6144
#define E3   (3 * Dc)     // 2304

// Scratch (allocation-free rule -> device globals)
__device__ float g_qkv[(size_t)NH * 3 * Bc * DHc];   // [n][qkv][b][dh], tf32 bits
__device__ float g_ctx[(size_t)NTOK * Dc];           // [b][s][d], tf32 bits
__device__ float g_Xc[(size_t)NTOK * Dc];            // tf32(X)
__device__ float g_Wq[(size_t)E3 * Dc];              // tf32(W_qkv)
__device__ float g_Wd[(size_t)Dc * Dc];              // tf32(W_dense)

// ---------------------------------------------------------------- helpers
__device__ __forceinline__ uint32_t f2tf32(float x) {
    uint32_t r;
    asm("cvt.rna.tf32.f32 %0, %1;" : "=r"(r) : "f"(x));
    return r;
}

__device__ __forceinline__ void mma_tf32(float* c, const uint32_t* a,
                                         const uint32_t* b)
{
    asm volatile(
        "mma.sync.aligned.m16n8k8.row.col.f32.tf32.tf32.f32 "
        "{%0,%1,%2,%3}, {%4,%5,%6,%7}, {%8,%9}, {%0,%1,%2,%3};"
        : "+f"(c[0]), "+f"(c[1]), "+f"(c[2]), "+f"(c[3])
        : "r"(a[0]), "r"(a[1]), "r"(a[2]), "r"(a[3]),
          "r"(b[0]), "r"(b[1]));
}

__device__ __forceinline__ uint32_t smem_u32(const void* p) {
    uint32_t a;
    asm("{ .reg .u64 t; cvta.to.shared.u64 t, %1; cvt.u32.u64 %0, t; }"
        : "=r"(a) : "l"(p));
    return a;
}
__device__ __forceinline__ void cp_async16(uint32_t dst, const void* src) {
    asm volatile("cp.async.cg.shared.global [%0], [%1], 16;"
                 :: "r"(dst), "l"(src));
}
#define CP_COMMIT() asm volatile("cp.async.commit_group;" ::: "memory")
#define CP_WAIT2()  asm volatile("cp.async.wait_group 2;" ::: "memory")

// ---------------------------------------------------------------- prep
// tf32-round whole tensors once: which 0->g_Xc, 1->g_Wq, 2->g_Wd
__global__ __launch_bounds__(256) void prep_cvt(const float4* __restrict__ src,
                                                int n4, int which)
{
    float4* dst = (which == 0) ? (float4*)g_Xc
                : (which == 1) ? (float4*)g_Wq : (float4*)g_Wd;
    int i = blockIdx.x * blockDim.x + threadIdx.x;
    if (i < n4) {
        float4 v = src[i];
        v.x = __uint_as_float(f2tf32(v.x));
        v.y = __uint_as_float(f2tf32(v.y));
        v.z = __uint_as_float(f2tf32(v.z));
        v.w = __uint_as_float(f2tf32(v.w));
        dst[i] = v;
    }
}

// ---------------------------------------------------------------- tc GEMM
// C[M,N] = A[M,K] * W[N,K]^T; inputs already tf32-rounded (no cvt in loop).
// CTA 128x128, BK=16, 8 warps (2x4, 64x32), 4-stage cp.async, SSTR=20.
#define BK    16
#define SSTR  20
#define TSZ   (128 * SSTR)                 // 2560 words / tile
#define SMEM_GEMM (8 * TSZ * 4)            // 81920 B

template <int MODE>
__global__ __launch_bounds__(256, 2) void gemm_mma(
    const float* __restrict__ bias, float* __restrict__ Cout,
    int K, int N)
{
    extern __shared__ uint32_t dynsm[];
    uint32_t* As = dynsm;                  // [4][TSZ]
    uint32_t* Ws = dynsm + 4 * TSZ;        // [4][TSZ]

    const float* Ap = (MODE == 1) ? (const float*)g_ctx : (const float*)g_Xc;
    const float* Wp = (MODE == 1) ? (const float*)g_Wd  : (const float*)g_Wq;

    const int tid  = threadIdx.x;
    const int lane = tid & 31;
    const int warp = tid >> 5;
    const int wm   = warp & 1;
    const int wn   = warp >> 1;
    const int g    = lane >> 2;
    const int t4   = lane & 3;

    const int rowBase = blockIdx.y * 128;
    const int colBase = blockIdx.x * 128;

    const int lr = tid >> 1;
    const int lc = (tid & 1) * 8;

    const float* gA = Ap + (size_t)(rowBase + lr) * K + lc;
    const float* gW = Wp + (size_t)(colBase + lr) * K + lc;

    const uint32_t sA = smem_u32(As) + (uint32_t)(lr * SSTR + lc) * 4;
    const uint32_t sW = smem_u32(Ws) + (uint32_t)(lr * SSTR + lc) * 4;

    const int nch = K / BK;   // 48

#pragma unroll
    for (int p = 0; p < 3; p++) {
        uint32_t da = sA + (uint32_t)((p & 3) * TSZ) * 4;
        uint32_t dw = sW + (uint32_t)((p & 3) * TSZ) * 4;
        const float* ga = gA + p * BK;
        const float* gw = gW + p * BK;
        cp_async16(da,      ga);
        cp_async16(da + 16, ga + 4);
        cp_async16(dw,      gw);
        cp_async16(dw + 16, gw + 4);
        CP_COMMIT();
    }

    float acc[4][4][4];
#pragma unroll
    for (int i = 0; i < 4; i++)
#pragma unroll
        for (int j = 0; j < 4; j++)
#pragma unroll
            for (int k = 0; k < 4; k++) acc[i][j][k] = 0.f;

    for (int ch = 0; ch < nch; ch++) {
        CP_WAIT2();
        __syncthreads();

        if (ch + 3 < nch) {
            int st = (ch + 3) & 3;
            uint32_t da = sA + (uint32_t)(st * TSZ) * 4;
            uint32_t dw = sW + (uint32_t)(st * TSZ) * 4;
            const float* ga = gA + (ch + 3) * BK;
            const float* gw = gW + (ch + 3) * BK;
            cp_async16(da,      ga);
            cp_async16(da + 16, ga + 4);
            cp_async16(dw,      gw);
            cp_async16(dw + 16, gw + 4);
        }
        CP_COMMIT();

        const uint32_t* Ab = As + (ch & 3) * TSZ;
        const uint32_t* Wb = Ws + (ch & 3) * TSZ;
#pragma unroll
        for (int ks = 0; ks < 2; ks++) {
            const int k0 = ks * 8;
            uint32_t af[4][4], bf[4][2];
#pragma unroll
            for (int mt = 0; mt < 4; mt++) {
                int r0 = wm * 64 + mt * 16 + g;
                af[mt][0] = Ab[(r0)     * SSTR + k0 + t4];
                af[mt][1] = Ab[(r0 + 8) * SSTR + k0 + t4];
                af[mt][2] = Ab[(r0)     * SSTR + k0 + t4 + 4];
                af[mt][3] = Ab[(r0 + 8) * SSTR + k0 + t4 + 4];
            }
#pragma unroll
            for (int nt = 0; nt < 4; nt++) {
                int c0 = wn * 32 + nt * 8 + g;
                bf[nt][0] = Wb[c0 * SSTR + k0 + t4];
                bf[nt][1] = Wb[c0 * SSTR + k0 + t4 + 4];
            }
#pragma unroll
            for (int mt = 0; mt < 4; mt++)
#pragma unroll
                for (int nt = 0; nt < 4; nt++)
                    mma_tf32(acc[mt][nt], af[mt], bf[nt]);
        }
    }

    // ---- epilogue ----
#pragma unroll
    for (int mt = 0; mt < 4; mt++) {
#pragma unroll
        for (int nt = 0; nt < 4; nt++) {
#pragma unroll
            for (int hi = 0; hi < 2; hi++) {
                int r = rowBase + wm * 64 + mt * 16 + g + hi * 8;
                int c = colBase + wn * 32 + nt * 8 + 2 * t4;
                float v0 = acc[mt][nt][hi * 2 + 0];
                float v1 = acc[mt][nt][hi * 2 + 1];
                if (MODE == 0) {
                    int b  = r >> 9;
                    int ss = r & 511;
#pragma unroll
                    for (int q = 0; q < 2; q++) {
                        int e = c + q;
                        float v = (q ? v1 : v0) + bias[e];
                        int h = e / 192, rr = e - h * 192;
                        int w = rr >> 6, dh = rr & 63;
                        int n = ss * Hc + h;
                        // store tf32-rounded bits (consumed by attention mma)
                        g_qkv[(((size_t)n * 3 + w) * Bc + b) * DHc + dh] =
                            __uint_as_float(f2tf32(v));
                    }
                } else {
                    float2* dst = (float2*)(Cout + (size_t)r * N + c);
                    *dst = make_float2(v0, v1);   // final output: full fp32
                }
            }
        }
    }
}

// ---------------------------------------------------------------- attention
// one CTA per n; inputs in g_qkv are already tf32 bits -> staging is bit-copy.
#define QP 68
#define PP 132
#define OFF_KS (128 * QP)
#define OFF_VT (2 * 128 * QP)
#define ATTN_FLOATS (OFF_VT + 64 * PP)
#define SMEM_ATTN (ATTN_FLOATS * 4)

__global__ __launch_bounds__(256, 1) void attn_kernel()
{
    extern __shared__ float sm[];
    uint32_t* Qs = (uint32_t*)sm;
    uint32_t* Ks = (uint32_t*)sm + OFF_KS;
    uint32_t* Vt = (uint32_t*)sm + OFF_VT;
    float*    Ps = sm;

    const int n   = blockIdx.x;
    const int tid = threadIdx.x;
    const int lane = tid & 31;
    const int warp = tid >> 5;
    const int wm = warp & 1;
    const int wn = warp >> 1;
    const int g  = lane >> 2;
    const int t4 = lane & 3;

    const uint32_t* qb = (const uint32_t*)(g_qkv + (size_t)n * 3 * Bc * DHc);
    const uint32_t* kb = qb + Bc * DHc;
    const uint32_t* vb = kb + Bc * DHc;

#pragma unroll
    for (int it = 0; it < 32; it++) {
        int idx = tid + it * 256;
        int r  = idx >> 6;
        int dh = idx & 63;
        Qs[r * QP + dh] = qb[idx];
        Ks[r * QP + dh] = kb[idx];
        Vt[dh * PP + r] = vb[idx];
    }
    __syncthreads();

    float acc[4][4][4];
#pragma unroll
    for (int i = 0; i < 4; i++)
#pragma unroll
        for (int j = 0; j < 4; j++)
#pragma unroll
            for (int k = 0; k < 4; k++) acc[i][j][k] = 0.f;

#pragma unroll
    for (int ks = 0; ks < 8; ks++) {
        const int k0 = ks * 8;
        uint32_t af[4][4], bf[4][2];
#pragma unroll
        for (int mt = 0; mt < 4; mt++) {
            int r0 = wm * 64 + mt * 16 + g;
            af[mt][0] = Qs[(r0)     * QP + k0 + t4];
            af[mt][1] = Qs[(r0 + 8) * QP + k0 + t4];
            af[mt][2] = Qs[(r0)     * QP + k0 + t4 + 4];
            af[mt][3] = Qs[(r0 + 8) * QP + k0 + t4 + 4];
        }
#pragma unroll
        for (int nt = 0; nt < 4; nt++) {
            int c0 = wn * 32 + nt * 8 + g;
            bf[nt][0] = Ks[c0 * QP + k0 + t4];
            bf[nt][1] = Ks[c0 * QP + k0 + t4 + 4];
        }
#pragma unroll
        for (int mt = 0; mt < 4; mt++)
#pragma unroll
            for (int nt = 0; nt < 4; nt++)
                mma_tf32(acc[mt][nt], af[mt], bf[nt]);
    }
    __syncthreads();

    const float scale = 0.125f;
#pragma unroll
    for (int mt = 0; mt < 4; mt++)
#pragma unroll
        for (int nt = 0; nt < 4; nt++)
#pragma unroll
            for (int hi = 0; hi < 2; hi++) {
                int r = wm * 64 + mt * 16 + g + hi * 8;
                int c = wn * 32 + nt * 8 + 2 * t4;
#pragma unroll
                for (int q = 0; q < 2; q++) {
                    float s = acc[mt][nt][hi * 2 + q] * scale;
                    if (c + q <= r) s = -10000.0f;
                    Ps[r * PP + c + q] = s;
                }
            }
    __syncthreads();

    for (int r = warp; r < 128; r += 8) {
        float v0 = Ps[r * PP + lane];
        float v1 = Ps[r * PP + lane + 32];
        float v2 = Ps[r * PP + lane + 64];
        float v3 = Ps[r * PP + lane + 96];
        float mx = fmaxf(fmaxf(v0, v1), fmaxf(v2, v3));
#pragma unroll
        for (int o = 16; o > 0; o >>= 1)
            mx = fmaxf(mx, __shfl_xor_sync(0xffffffffu, mx, o));
        float e0 = __expf(v0 - mx), e1 = __expf(v1 - mx);
        float e2 = __expf(v2 - mx), e3 = __expf(v3 - mx);
        float sum = e0 + e1 + e2 + e3;
#pragma unroll
        for (int o = 16; o > 0; o >>= 1)
            sum += __shfl_xor_sync(0xffffffffu, sum, o);
        float inv = 1.0f / sum;
        Ps[r * PP + lane]      = __uint_as_float(f2tf32(e0 * inv));
        Ps[r * PP + lane + 32] = __uint_as_float(f2tf32(e1 * inv));
        Ps[r * PP + lane + 64] = __uint_as_float(f2tf32(e2 * inv));
        Ps[r * PP + lane + 96] = __uint_as_float(f2tf32(e3 * inv));
    }
    __syncthreads();

    const uint32_t* Pu = (const uint32_t*)Ps;
    float acc2[4][2][4];
#pragma unroll
    for (int i = 0; i < 4; i++)
#pragma unroll
        for (int j = 0; j < 2; j++)
#pragma unroll
            for (int k = 0; k < 4; k++) acc2[i][j][k] = 0.f;

#pragma unroll
    for (int ks = 0; ks < 16; ks++) {
        const int k0 = ks * 8;
        uint32_t af[4][4], bf[2][2];
#pragma unroll
        for (int mt = 0; mt < 4; mt++) {
            int r0 = wm * 64 + mt * 16 + g;
            af[mt][0] = Pu[(r0)     * PP + k0 + t4];
            af[mt][1] = Pu[(r0 + 8) * PP + k0 + t4];
            af[mt][2] = Pu[(r0)     * PP + k0 + t4 + 4];
            af[mt][3] = Pu[(r0 + 8) * PP + k0 + t4 + 4];
        }
#pragma unroll
        for (int nt = 0; nt < 2; nt++) {
            int c0 = wn * 16 + nt * 8 + g;
            bf[nt][0] = Vt[c0 * PP + k0 + t4];
            bf[nt][1] = Vt[c0 * PP + k0 + t4 + 4];
        }
#pragma unroll
        for (int mt = 0; mt < 4; mt++)
#pragma unroll
            for (int nt = 0; nt < 2; nt++)
                mma_tf32(acc2[mt][nt], af[mt], bf[nt]);
    }

    const int s = n / Hc;
    const int h = n - s * Hc;
#pragma unroll
    for (int mt = 0; mt < 4; mt++)
#pragma unroll
        for (int nt = 0; nt < 2; nt++)
#pragma unroll
            for (int hi = 0; hi < 2; hi++) {
                int b  = wm * 64 + mt * 16 + g + hi * 8;
                int dh = wn * 16 + nt * 8 + 2 * t4;
                float2* dst = (float2*)(g_ctx +
                    ((size_t)b * Sc + s) * Dc + h * 64 + dh);
                // tf32-rounded bits (consumed by dense GEMM without cvt)
                *dst = make_float2(
                    __uint_as_float(f2tf32(acc2[mt][nt][hi * 2 + 0])),
                    __uint_as_float(f2tf32(acc2[mt][nt][hi * 2 + 1])));
            }
}

// ----------------------------------------------------------------
extern "C" void kernel_launch(void* const* d_in, const int* in_sizes, int n_in,
                              void* d_out, int out_size)
{
    const float* X       = (const float*)d_in[0];
    const float* W_qkv   = (const float*)d_in[1];
    const float* b_qkv   = (const float*)d_in[2];
    const float* W_dense = (const float*)d_in[3];
    const float* b_dense = (const float*)d_in[4];
    float* out = (float*)d_out;
    (void)in_sizes; (void)n_in;

    cudaFuncSetAttribute(gemm_mma<0>,
                         cudaFuncAttributeMaxDynamicSharedMemorySize, SMEM_GEMM);
    cudaFuncSetAttribute(gemm_mma<1>,
                         cudaFuncAttributeMaxDynamicSharedMemorySize, SMEM_GEMM);
    cudaFuncSetAttribute(attn_kernel,
                         cudaFuncAttributeMaxDynamicSharedMemorySize, SMEM_ATTN);

    // 0) one-time tf32 rounding passes
    {
        int n4x = NTOK * Dc / 4;          // 12,582,912
        prep_cvt<<<(n4x + 255) / 256, 256>>>((const float4*)X, n4x, 0);
        int n4q = E3 * Dc / 4;            // 442,368
        prep_cvt<<<(n4q + 255) / 256, 256>>>((const float4*)W_qkv, n4q, 1);
        int n4d = Dc * Dc / 4;            // 147,456
        prep_cvt<<<(n4d + 255) / 256, 256>>>((const float4*)W_dense, n4d, 2);
    }

    // 1) QKV = tf32(X) @ tf32(W_qkv)^T + bias -> g_qkv (tf32 bits)
    gemm_mma<0><<<dim3(E3 / 128, NTOK / 128), 256, SMEM_GEMM>>>(
        b_qkv, nullptr, Dc, E3);

    // 2) attention
    attn_kernel<<<NH, 256, SMEM_ATTN>>>();

    // 3) out = ctx @ tf32(W_dense)^T
    gemm_mma<1><<<dim3(Dc / 128, NTOK / 128), 256, SMEM_GEMM>>>(
        nullptr, out, Dc, Dc);

    // 4) tail: reference returns (out, b_dense)
    long long tail = (long long)out_size - (long long)NTOK * Dc;
    if (tail > 0) {
        if (tail > Dc) tail = Dc;
        cudaMemcpyAsync(out + (size_t)NTOK * Dc, b_dense,
                        (size_t)tail * sizeof(float),
                        cudaMemcpyDeviceToDevice, 0);
    }
}